// round 7
// baseline (speedup 1.0000x reference)
#include <cuda_runtime.h>
#include <cstdint>

#define D_BINS 59
#define C_CH   80
#define O_TOT  139
#define WSROW  148   // padded smem row for weights
#define B_     4
#define N_     6
#define CIN    256
#define H_     16
#define W_     44
#define HW     704              // H_*W_
#define NPIX   (B_*N_*H_*W_)    // 16896
#define NCELL  (B_*128*128)     // 65536
#define BEVW   128
#define NPAIR  (D_BINS*W_)      // 2596 (d,w) pairs per conv block
#define CAP    64               // bin capacity: Poisson(15.2), P(>=64) ~ 1e-28/cell — safe.
                                // (CAP=32 overflowed ~6 cells/launch -> e-3 rel_err. Never again.)

// ---- device scratch (no allocations allowed; zero-initialized at load) ----
__device__ float4 g_ctx[NPIX*20];          // [pix][c4] fp32 ctx, 5.4 MB (L2-resident)
__device__ int    g_cnt[NCELL];            // per-cell counts (reset by gather)
__device__ int2   g_bin[NCELL*CAP];        // {pix, depth-bits}, 33.5 MB

// ============================================================================
// K1: FUSED conv(139x44x256) + softmax(59) + ctx store + cell binning.
// One block per (b,n,h) row: 384 blocks, 224 threads, 48KB dynamic smem.
// ============================================================================
__global__ __launch_bounds__(224) void conv_bin_kernel(
    const float* __restrict__ img, const float* __restrict__ wd,
    const float* __restrict__ bd,  const int*   __restrict__ geom)
{
    extern __shared__ float sm[];
    // compute-phase layout
    float* ws = sm;                 // [64][WSROW] weight chunk (c-major)
    float* xs = sm + 64 * WSROW;    // [64][44]    input chunk (total 12288 floats)
    // post-GEMM layout (reused after syncs)
    float* xo_d   = sm;                    // [59][44] depth logits   (2596)
    float* s_dep  = sm + NPAIR;            // [59][44] softmaxed      (2596)
    float* s_ctx  = sm + 2 * NPAIR;        // [44][80] context        (3520, 16B-aligned)
    int*   s_cell = (int*)(sm + 2 * NPAIR + W_ * C_CH);  // [59][44]  (2596)

    const int tid = threadIdx.x;
    const int row = blockIdx.x;             // bn*16 + h
    const int bn  = row >> 4;
    const int h   = row & 15;
    const int b   = bn / N_;
    const float* src = img + (size_t)bn * CIN * HW + h * W_;
    const float4* w4 = (const float4*)wd;   // [139][64] float4

    const int wt = tid % 11;   // w-tile (4 w's)
    const int ot = tid / 11;   // o-tile (8 o's), valid for tid < 198

    float acc[8][4];
#pragma unroll
    for (int j = 0; j < 8; j++)
#pragma unroll
        for (int k = 0; k < 4; k++) acc[j][k] = 0.f;

    // ---------------- GEMM: 4 chunks of 64 input channels ----------------
    for (int ck = 0; ck < 4; ck++) {
        __syncthreads();
        for (int i = tid; i < O_TOT * 16; i += 224) {
            int o  = i >> 4;
            int c4 = i & 15;
            float4 v = w4[o * 64 + ck * 16 + c4];
            int c = c4 * 4;
            ws[(c + 0) * WSROW + o] = v.x;
            ws[(c + 1) * WSROW + o] = v.y;
            ws[(c + 2) * WSROW + o] = v.z;
            ws[(c + 3) * WSROW + o] = v.w;
        }
        for (int i = tid; i < 64 * W_; i += 224) {
            int c = i / W_;
            int w = i - c * W_;
            xs[i] = src[(ck * 64 + c) * HW + w];
        }
        __syncthreads();

        if (tid < 198) {
#pragma unroll 2
            for (int c = 0; c < 64; c++) {
                float4 xv = *(const float4*)&xs[c * W_ + wt * 4];
                float4 wa = *(const float4*)&ws[c * WSROW + ot * 8];
                float4 wb = *(const float4*)&ws[c * WSROW + ot * 8 + 4];
                float wv[8] = {wa.x, wa.y, wa.z, wa.w, wb.x, wb.y, wb.z, wb.w};
                float xr[4] = {xv.x, xv.y, xv.z, xv.w};
#pragma unroll
                for (int j = 0; j < 8; j++)
#pragma unroll
                    for (int k = 0; k < 4; k++) acc[j][k] += wv[j] * xr[k];
            }
        }
    }

    __syncthreads();
    // ------- dump: depth logits -> xo_d[d][w]; context -> s_ctx[w][c] -------
    if (tid < 198) {
#pragma unroll
        for (int j = 0; j < 8; j++) {
            int o = ot * 8 + j;
            if (o < O_TOT) {
                float bias = __ldg(&bd[o]);
#pragma unroll
                for (int k = 0; k < 4; k++) {
                    int w = wt * 4 + k;
                    float v = acc[j][k] + bias;
                    if (o < D_BINS) xo_d[o * W_ + w] = v;
                    else            s_ctx[w * C_CH + (o - D_BINS)] = v;
                }
            }
        }
    }
    // ------- stage geom cells (global latency overlapped with dump) -------
    {
        const int2* g2 = (const int2*)geom;
        const int cbase = bn * D_BINS * HW + h * W_;
        for (int i = tid; i < NPAIR; i += 224) {
            int d = i / W_;
            int w = i - d * W_;
            int2 g = __ldg(&g2[cbase + d * HW + w]);
            s_cell[i] = (b << 14) + g.x * BEVW + g.y;
        }
    }
    __syncthreads();

    // ------- store fp32 context to global (overlaps softmax below) -------
    {
        const float4* cs = (const float4*)s_ctx;
        float4* cg = g_ctx + (size_t)row * W_ * 20;
        for (int i = tid; i < W_ * 20; i += 224)
            cg[i] = cs[i];
    }

    // ---------------- softmax over 59 bins; one warp per column ----------------
    const int warp = tid >> 5;
    const int lane = tid & 31;
    for (int w = warp; w < W_; w += 7) {
        float v0 = (lane < D_BINS)        ? xo_d[lane * W_ + w]        : -1e30f;
        float v1 = ((lane + 32) < D_BINS) ? xo_d[(lane + 32) * W_ + w] : -1e30f;
        float m = fmaxf(v0, v1);
#pragma unroll
        for (int off = 16; off; off >>= 1)
            m = fmaxf(m, __shfl_xor_sync(0xffffffffu, m, off));
        float e0 = (lane < D_BINS)        ? expf(v0 - m) : 0.f;
        float e1 = ((lane + 32) < D_BINS) ? expf(v1 - m) : 0.f;
        float s = e0 + e1;
#pragma unroll
        for (int off = 16; off; off >>= 1)
            s += __shfl_xor_sync(0xffffffffu, s, off);
        float inv = 1.0f / s;
        if (lane < D_BINS)        s_dep[lane * W_ + w]        = e0 * inv;
        if ((lane + 32) < D_BINS) s_dep[(lane + 32) * W_ + w] = e1 * inv;
    }
    __syncthreads();

    // ------- bin the 2596 points: slot = atomicAdd(cnt), write {pix, dep} -------
    const int pixbase = row * W_;
    for (int p = tid; p < NPAIR; p += 224) {
        int w = p % W_;
        int cell = s_cell[p];
        int slot = atomicAdd(&g_cnt[cell], 1);
        if (slot < CAP)
            g_bin[cell * CAP + slot] =
                make_int2(pixbase + w, __float_as_int(s_dep[p]));
    }
}

// ============================================================================
// K2: GATHER per BEV cell + transposed coalesced output write + counter reset.
// 1024 blocks x 256 threads; block = 64 cells, warp = 8 cells.
// All <=64 records of a cell loaded with ONE coalesced int4 warp load
// (lane l -> slots 2l, 2l+1), then shfl-broadcast per point: every ctx-load
// address is known before the FMAs -> compiler pipelines the LDGs (high MLP).
// ============================================================================
__global__ __launch_bounds__(256) void gather_kernel(float* __restrict__ out)
{
    __shared__ float t[C_CH * 65];   // [c][64+1 pad] 20.8 KB, conflict-free
    const int b     = blockIdx.x >> 8;
    const int yx0   = (blockIdx.x & 255) * 64;
    const int warp  = threadIdx.x >> 5;
    const int lane  = threadIdx.x & 31;
    const int4* bin4 = (const int4*)g_bin;   // 2 records per int4

#pragma unroll
    for (int cc = 0; cc < 8; cc++) {
        const int cl   = warp * 8 + cc;          // local cell 0..63
        const int cell = (b << 14) + yx0 + cl;

        int cnt0 = 0;
        if (lane == 0) {
            cnt0 = g_cnt[cell];
            g_cnt[cell] = 0;                     // reset for next graph replay
        }
        int cnt = __shfl_sync(0xffffffffu, cnt0, 0);
        if (cnt > CAP) cnt = CAP;

        // one coalesced load covers all 64 record slots of this cell
        int4 r = make_int4(0, 0, 0, 0);
        if (lane * 2 < cnt) r = __ldg(&bin4[cell * (CAP / 2) + lane]);

        float4 acc = make_float4(0.f, 0.f, 0.f, 0.f);
#pragma unroll 4
        for (int pt = 0; pt < cnt; pt++) {
            int src = pt >> 1;
            int   pix, depi;
            if (pt & 1) {
                pix  = __shfl_sync(0xffffffffu, r.z, src);
                depi = __shfl_sync(0xffffffffu, r.w, src);
            } else {
                pix  = __shfl_sync(0xffffffffu, r.x, src);
                depi = __shfl_sync(0xffffffffu, r.y, src);
            }
            float dep = __int_as_float(depi);
            if (lane < 20) {
                float4 cv = __ldg(&g_ctx[pix * 20 + lane]);
                acc.x += dep * cv.x;
                acc.y += dep * cv.y;
                acc.z += dep * cv.z;
                acc.w += dep * cv.w;
            }
        }
        if (lane < 20) {
            int c = lane * 4;
            t[(c + 0) * 65 + cl] = acc.x;
            t[(c + 1) * 65 + cl] = acc.y;
            t[(c + 2) * 65 + cl] = acc.z;
            t[(c + 3) * 65 + cl] = acc.w;
        }
    }
    __syncthreads();

    float* dst = out + ((size_t)b * C_CH) * (128 * 128) + yx0;
#pragma unroll
    for (int i = threadIdx.x; i < C_CH * 64; i += 256) {
        int c = i >> 6;
        int j = i & 63;
        dst[(size_t)c * (128 * 128) + j] = t[c * 65 + j];
    }
}

// ============================================================================
extern "C" void kernel_launch(void* const* d_in, const int* in_sizes, int n_in,
                              void* d_out, int out_size)
{
    const float* img  = (const float*)d_in[0];
    const float* wd   = (const float*)d_in[4];
    const float* bd   = (const float*)d_in[5];
    const int*   geom = (const int*)d_in[6];
    float* out = (float*)d_out;

    conv_bin_kernel<<<B_ * N_ * H_, 224, (64 * WSROW + 64 * W_) * 4>>>(img, wd, bd, geom);
    gather_kernel<<<B_ * 256, 256>>>(out);
}

// round 8
// speedup vs baseline: 1.2607x; 1.2607x over previous
#include <cuda_runtime.h>
#include <cstdint>

#define D_BINS 59
#define C_CH   80
#define O_TOT  139
#define WSROW  148   // padded smem row for weights
#define B_     4
#define N_     6
#define CIN    256
#define H_     16
#define W_     44
#define HW     704              // H_*W_
#define NPIX   (B_*N_*H_*W_)    // 16896
#define NCELL  (B_*128*128)     // 65536
#define BEVW   128
#define NPAIR  (D_BINS*W_)      // 2596 (d,w) pairs per conv block
#define CAP    64               // bin capacity: Poisson(15.2), P(>=64) ~ 1e-28/cell — safe.
#define STAGE  32               // records staged in smem per cell (cnt>32 -> slow path)
#define GCELLS 32               // cells per gather block

// ---- device scratch (no allocations allowed; zero-initialized at load) ----
__device__ float4 g_ctx[NPIX*20];          // [pix][c4] fp32 ctx, 5.4 MB (L2-resident)
__device__ int    g_cnt[NCELL];            // per-cell counts (reset by gather)
__device__ int2   g_bin[NCELL*CAP];        // {pix, depth-bits}, 33.5 MB

// ============================================================================
// K1: FUSED conv(139x44x256) + softmax(59) + ctx store + cell binning.
// One block per (b,n,h) row: 384 blocks, 224 threads.
// 8 chunks of 32 input channels; NEXT chunk's weights prefetched into
// registers before the barrier -> weight-load latency hidden under compute.
// ============================================================================
__global__ __launch_bounds__(224, 3) void conv_bin_kernel(
    const float* __restrict__ img, const float* __restrict__ wd,
    const float* __restrict__ bd,  const int*   __restrict__ geom)
{
    extern __shared__ float sm[];
    // compute-phase layout
    float* ws = sm;                 // [32][WSROW] weight chunk (c-major)
    float* xs = sm + 32 * WSROW;    // [32][44]    input chunk  (6144 floats total)
    // post-GEMM layout (reused after syncs)
    float* xo_d   = sm;                    // [59][44] depth logits   (2596)
    float* s_dep  = sm + NPAIR;            // [59][44] softmaxed      (2596)
    float* s_ctx  = sm + 2 * NPAIR;        // [44][80] context        (3520, 16B-aligned)
    int*   s_cell = (int*)(sm + 2 * NPAIR + W_ * C_CH);  // [59][44]  (2596)

    const int tid = threadIdx.x;
    const int row = blockIdx.x;             // bn*16 + h
    const int bn  = row >> 4;
    const int h   = row & 15;
    const int b   = bn / N_;
    const float* src = img + (size_t)bn * CIN * HW + h * W_;
    const float4* w4 = (const float4*)wd;   // [139][64] float4

    const int wt = tid % 11;   // w-tile (4 w's)
    const int ot = tid / 11;   // o-tile (8 o's), valid for tid < 198

    float acc[8][4];
#pragma unroll
    for (int j = 0; j < 8; j++)
#pragma unroll
        for (int k = 0; k < 4; k++) acc[j][k] = 0.f;

    // prefetch chunk 0 weights into registers: i = o*8 + c8 (139*8 = 1112)
    float4 wpre[5];
#pragma unroll
    for (int r = 0; r < 5; r++) {
        int i = tid + 224 * r;
        if (i < O_TOT * 8) wpre[r] = w4[(i >> 3) * 64 + (i & 7)];
    }

    // ---------------- GEMM: 8 chunks of 32 input channels ----------------
    for (int ck = 0; ck < 8; ck++) {
        __syncthreads();
        // store prefetched weights (transposed c-major) into smem
#pragma unroll
        for (int r = 0; r < 5; r++) {
            int i = tid + 224 * r;
            if (i < O_TOT * 8) {
                int o = i >> 3;
                int c = (i & 7) * 4;
                float4 v = wpre[r];
                ws[(c + 0) * WSROW + o] = v.x;
                ws[(c + 1) * WSROW + o] = v.y;
                ws[(c + 2) * WSROW + o] = v.z;
                ws[(c + 3) * WSROW + o] = v.w;
            }
        }
        // load input chunk
        for (int i = tid; i < 32 * W_; i += 224) {
            int c = i / W_;
            int w = i - c * W_;
            xs[i] = src[(ck * 32 + c) * HW + w];
        }
        // issue prefetch of NEXT chunk's weights (lands during compute)
        if (ck < 7) {
#pragma unroll
            for (int r = 0; r < 5; r++) {
                int i = tid + 224 * r;
                if (i < O_TOT * 8)
                    wpre[r] = w4[(i >> 3) * 64 + (ck + 1) * 8 + (i & 7)];
            }
        }
        __syncthreads();

        if (tid < 198) {
#pragma unroll 2
            for (int c = 0; c < 32; c++) {
                float4 xv = *(const float4*)&xs[c * W_ + wt * 4];
                float4 wa = *(const float4*)&ws[c * WSROW + ot * 8];
                float4 wb = *(const float4*)&ws[c * WSROW + ot * 8 + 4];
                float wv[8] = {wa.x, wa.y, wa.z, wa.w, wb.x, wb.y, wb.z, wb.w};
                float xr[4] = {xv.x, xv.y, xv.z, xv.w};
#pragma unroll
                for (int j = 0; j < 8; j++)
#pragma unroll
                    for (int k = 0; k < 4; k++) acc[j][k] += wv[j] * xr[k];
            }
        }
    }

    __syncthreads();
    // ------- dump: depth logits -> xo_d[d][w]; context -> s_ctx[w][c] -------
    if (tid < 198) {
#pragma unroll
        for (int j = 0; j < 8; j++) {
            int o = ot * 8 + j;
            if (o < O_TOT) {
                float bias = __ldg(&bd[o]);
#pragma unroll
                for (int k = 0; k < 4; k++) {
                    int w = wt * 4 + k;
                    float v = acc[j][k] + bias;
                    if (o < D_BINS) xo_d[o * W_ + w] = v;
                    else            s_ctx[w * C_CH + (o - D_BINS)] = v;
                }
            }
        }
    }
    // ------- stage geom cells (global latency overlapped with dump) -------
    {
        const int2* g2 = (const int2*)geom;
        const int cbase = bn * D_BINS * HW + h * W_;
        for (int i = tid; i < NPAIR; i += 224) {
            int d = i / W_;
            int w = i - d * W_;
            int2 g = __ldg(&g2[cbase + d * HW + w]);
            s_cell[i] = (b << 14) + g.x * BEVW + g.y;
        }
    }
    __syncthreads();

    // ------- store fp32 context to global (overlaps softmax below) -------
    {
        const float4* cs = (const float4*)s_ctx;
        float4* cg = g_ctx + (size_t)row * W_ * 20;
        for (int i = tid; i < W_ * 20; i += 224)
            cg[i] = cs[i];
    }

    // ---------------- softmax over 59 bins; one warp per column ----------------
    const int warp = tid >> 5;
    const int lane = tid & 31;
    for (int w = warp; w < W_; w += 7) {
        float v0 = (lane < D_BINS)        ? xo_d[lane * W_ + w]        : -1e30f;
        float v1 = ((lane + 32) < D_BINS) ? xo_d[(lane + 32) * W_ + w] : -1e30f;
        float m = fmaxf(v0, v1);
#pragma unroll
        for (int off = 16; off; off >>= 1)
            m = fmaxf(m, __shfl_xor_sync(0xffffffffu, m, off));
        float e0 = (lane < D_BINS)        ? expf(v0 - m) : 0.f;
        float e1 = ((lane + 32) < D_BINS) ? expf(v1 - m) : 0.f;
        float s = e0 + e1;
#pragma unroll
        for (int off = 16; off; off >>= 1)
            s += __shfl_xor_sync(0xffffffffu, s, off);
        float inv = 1.0f / s;
        if (lane < D_BINS)        s_dep[lane * W_ + w]        = e0 * inv;
        if ((lane + 32) < D_BINS) s_dep[(lane + 32) * W_ + w] = e1 * inv;
    }
    __syncthreads();

    // ------- bin the 2596 points: slot = atomicAdd(cnt), write {pix, dep} -------
    const int pixbase = row * W_;
    for (int p = tid; p < NPAIR; p += 224) {
        int w = p % W_;
        int cell = s_cell[p];
        int slot = atomicAdd(&g_cnt[cell], 1);
        if (slot < CAP)
            g_bin[cell * CAP + slot] =
                make_int2(pixbase + w, __float_as_int(s_dep[p]));
    }
}

// ============================================================================
// K2: GATHER per BEV cell. 2048 blocks x 128 threads; block = 32 cells,
// warp = 8 cells. Counts + first 32 records of every cell staged to smem
// with UNCONDITIONAL coalesced loads (no cnt dependency). Point loop runs in
// chunks of 4 with clamped smem indices + zeroed tail weights: all 4 ctx-LDG
// addresses come from static-offset LDS reads -> loads batch (MLP>=4),
// no shfl, no data-dependent branches. cnt>32 tail (P~9e-5/cell) reads gmem.
// ============================================================================
__global__ __launch_bounds__(128) void gather_kernel(float* __restrict__ out)
{
    __shared__ int2  s_rec[GCELLS * STAGE];      // 8 KB
    __shared__ int   s_cnt[GCELLS];
    __shared__ float t[C_CH * (GCELLS + 1)];     // [c][33] 10.6 KB

    const int tid  = threadIdx.x;
    const int warp = tid >> 5;
    const int lane = tid & 31;
    const int b    = blockIdx.x >> 9;            // 512 blocks per batch
    const int yx0  = (blockIdx.x & 511) * GCELLS;
    const int cell0 = (b << 14) + yx0;

    if (tid < GCELLS) {
        int c = g_cnt[cell0 + tid];
        g_cnt[cell0 + tid] = 0;                  // reset for next graph replay
        s_cnt[tid] = (c > CAP) ? CAP : c;
    }
    // stage first 32 record slots of each cell (unconditional, coalesced)
#pragma unroll
    for (int r = 0; r < GCELLS * STAGE / 128; r++) {
        int i  = tid + 128 * r;                  // i = cl*32 + slot
        int cl = i >> 5, slot = i & 31;
        s_rec[i] = g_bin[(cell0 + cl) * CAP + slot];
    }
    __syncthreads();

#pragma unroll
    for (int cc = 0; cc < 8; cc++) {
        const int cl  = warp * 8 + cc;           // local cell 0..31
        const int cnt = s_cnt[cl];
        const int cnt_s = (cnt < STAGE) ? cnt : STAGE;
        const int2* rec = &s_rec[cl * STAGE];

        float4 acc = make_float4(0.f, 0.f, 0.f, 0.f);
        for (int base = 0; base < cnt_s; base += 4) {
            int   pix[4];
            float dep[4];
#pragma unroll
            for (int u = 0; u < 4; u++) {
                int pt  = base + u;
                int idx = (pt < cnt_s) ? pt : (cnt_s - 1);
                int2 rr = rec[idx];              // LDS broadcast, static offset
                pix[u] = rr.x;
                dep[u] = (pt < cnt_s) ? __int_as_float(rr.y) : 0.f;
            }
            if (lane < 20) {
                float4 cv0 = __ldg(&g_ctx[pix[0] * 20 + lane]);
                float4 cv1 = __ldg(&g_ctx[pix[1] * 20 + lane]);
                float4 cv2 = __ldg(&g_ctx[pix[2] * 20 + lane]);
                float4 cv3 = __ldg(&g_ctx[pix[3] * 20 + lane]);
                acc.x += dep[0]*cv0.x; acc.y += dep[0]*cv0.y;
                acc.z += dep[0]*cv0.z; acc.w += dep[0]*cv0.w;
                acc.x += dep[1]*cv1.x; acc.y += dep[1]*cv1.y;
                acc.z += dep[1]*cv1.z; acc.w += dep[1]*cv1.w;
                acc.x += dep[2]*cv2.x; acc.y += dep[2]*cv2.y;
                acc.z += dep[2]*cv2.z; acc.w += dep[2]*cv2.w;
                acc.x += dep[3]*cv3.x; acc.y += dep[3]*cv3.y;
                acc.z += dep[3]*cv3.z; acc.w += dep[3]*cv3.w;
            }
        }
        // rare overflow tail: records beyond the staged 32
        for (int pt = STAGE; pt < cnt; pt++) {
            int2 rr = __ldg(&g_bin[(cell0 + cl) * CAP + pt]);
            float dep0 = __int_as_float(rr.y);
            if (lane < 20) {
                float4 cv = __ldg(&g_ctx[rr.x * 20 + lane]);
                acc.x += dep0 * cv.x; acc.y += dep0 * cv.y;
                acc.z += dep0 * cv.z; acc.w += dep0 * cv.w;
            }
        }
        if (lane < 20) {
            int c = lane * 4;
            t[(c + 0) * (GCELLS + 1) + cl] = acc.x;
            t[(c + 1) * (GCELLS + 1) + cl] = acc.y;
            t[(c + 2) * (GCELLS + 1) + cl] = acc.z;
            t[(c + 3) * (GCELLS + 1) + cl] = acc.w;
        }
    }
    __syncthreads();

    float* dst = out + ((size_t)b * C_CH) * (128 * 128) + yx0;
#pragma unroll
    for (int i = tid; i < C_CH * GCELLS; i += 128) {
        int c = i >> 5;
        int j = i & 31;
        dst[(size_t)c * (128 * 128) + j] = t[c * (GCELLS + 1) + j];
    }
}

// ============================================================================
extern "C" void kernel_launch(void* const* d_in, const int* in_sizes, int n_in,
                              void* d_out, int out_size)
{
    const float* img  = (const float*)d_in[0];
    const float* wd   = (const float*)d_in[4];
    const float* bd   = (const float*)d_in[5];
    const int*   geom = (const int*)d_in[6];
    float* out = (float*)d_out;

    // dynamic smem = max(compute phase 6144, post phase 11308) floats
    conv_bin_kernel<<<B_ * N_ * H_, 224, 11312 * 4>>>(img, wd, bd, geom);
    gather_kernel<<<2048, 128>>>(out);
}

// round 9
// speedup vs baseline: 1.3683x; 1.0854x over previous
#include <cuda_runtime.h>
#include <cstdint>

#define D_BINS 59
#define C_CH   80
#define O_TOT  139
#define B_     4
#define N_     6
#define CIN    256
#define H_     16
#define W_     44
#define HW     704              // H_*W_
#define NPIX   (B_*N_*H_*W_)    // 16896
#define NCELL  (B_*128*128)     // 65536
#define BEVW   128
#define NPAIR  (D_BINS*W_)      // 2596 (d,w) pairs per row
#define CAP    64               // bin capacity: Poisson(15.2), P(>=64)~1e-28/cell — safe
#define STAGE  32               // records staged in smem per cell in gather
#define GCELLS 32               // cells per gather block
#define OT3    48               // outputs per o-third (3*48 = 144 >= 139)
#define WPAD   48               // padded w per row

// ---- device scratch (no allocations; zero-initialized at load) ----
__device__ float g_dep[NPIX*64];           // [pix][o<59] depth logits->(K2: consumed) 4.3 MB
__device__ float g_ctx[NPIX*C_CH];         // [pix][c] fp32 ctx, 5.4 MB (L2-resident)
__device__ int   g_cnt[NCELL];             // per-cell counts (reset by gather)
__device__ int2  g_bin[NCELL*CAP];         // {pix, depth-bits}, 33.5 MB

// ============================================================================
// K1: GEMM only. Block = (row, o-third): 48 outs x 48 w(pad) x 256 c.
// 1152 blocks x 128 threads (4 warps -> perfect SMSP balance; 7.8 blk/SM ->
// wave skew 1.03). Tile 6o x 3w = 18 acc. Writes logits to g_dep / g_ctx.
// ============================================================================
__global__ __launch_bounds__(128) void gemm_kernel(
    const float* __restrict__ img, const float* __restrict__ wd,
    const float* __restrict__ bd)
{
    __shared__ float ws[32 * OT3];   // [c][48] weight chunk (c-major, o contiguous)
    __shared__ float xs[32 * WPAD];  // [c][48] input chunk (w 44..47 zeroed)

    const int tid   = threadIdx.x;
    const int blk   = blockIdx.x;
    const int row   = blk / 3;              // bn*16 + h
    const int third = blk - row * 3;
    const int bn    = row >> 4;
    const int h     = row & 15;
    const int o0    = third * OT3;
    const float* src = img + (size_t)bn * CIN * HW + h * W_;
    const float4* w4 = (const float4*)wd;   // [139][64] float4

    const int wt = tid & 15;   // w-tile (3 w's), 16 tiles
    const int ot = tid >> 4;   // o-tile (6 o's), 8 tiles

    float acc[6][3];
#pragma unroll
    for (int j = 0; j < 6; j++)
#pragma unroll
        for (int k = 0; k < 3; k++) acc[j][k] = 0.f;

    for (int ck = 0; ck < 8; ck++) {        // 8 chunks of 32 input channels
        __syncthreads();
        // stage weights: 48 o x 32 c -> ws[c][o] (padded o -> 0)
#pragma unroll
        for (int r = 0; r < 3; r++) {
            int idx = tid + 128 * r;        // 0..383 = o_l*8 + c4
            int o_l = idx >> 3;
            int c4  = idx & 7;
            float4 v = make_float4(0.f, 0.f, 0.f, 0.f);
            if (o0 + o_l < O_TOT) v = w4[(o0 + o_l) * 64 + ck * 8 + c4];
            int c = c4 * 4;
            ws[(c + 0) * OT3 + o_l] = v.x;
            ws[(c + 1) * OT3 + o_l] = v.y;
            ws[(c + 2) * OT3 + o_l] = v.z;
            ws[(c + 3) * OT3 + o_l] = v.w;
        }
        // stage inputs: 32 c x 48 w (w>=44 zero)
#pragma unroll
        for (int r = 0; r < 12; r++) {
            int i = tid + 128 * r;          // 0..1535
            int c = i / WPAD;
            int w = i - c * WPAD;
            xs[i] = (w < W_) ? src[(ck * 32 + c) * HW + w] : 0.f;
        }
        __syncthreads();

#pragma unroll 4
        for (int c = 0; c < 32; c++) {
            const float* wr = &ws[c * OT3 + ot * 6];
            float2 wa = *(const float2*)&wr[0];
            float2 wb = *(const float2*)&wr[2];
            float2 wc = *(const float2*)&wr[4];
            const float* xr = &xs[c * WPAD + wt * 3];
            float x0 = xr[0], x1 = xr[1], x2 = xr[2];
            float wv[6] = {wa.x, wa.y, wb.x, wb.y, wc.x, wc.y};
#pragma unroll
            for (int j = 0; j < 6; j++) {
                acc[j][0] += wv[j] * x0;
                acc[j][1] += wv[j] * x1;
                acc[j][2] += wv[j] * x2;
            }
        }
    }

    // store: depth logits -> g_dep[pix][o], ctx -> g_ctx[pix][o-59]
#pragma unroll
    for (int j = 0; j < 6; j++) {
        int o_g = o0 + ot * 6 + j;
        if (o_g < O_TOT) {
            float bias = __ldg(&bd[o_g]);
#pragma unroll
            for (int k = 0; k < 3; k++) {
                int w = wt * 3 + k;
                if (w < W_) {
                    int pix = row * W_ + w;
                    float v = acc[j][k] + bias;
                    if (o_g < D_BINS) g_dep[pix * 64 + o_g]          = v;
                    else              g_ctx[pix * C_CH + (o_g - D_BINS)] = v;
                }
            }
        }
    }
}

// ============================================================================
// K2: softmax(59) over g_dep + cell binning. 384 blocks (one per row) x 256.
// ============================================================================
__global__ __launch_bounds__(256) void softmax_bin_kernel(const int* __restrict__ geom)
{
    __shared__ float s_dep[NPAIR];     // [d][44]
    __shared__ int   s_cell[NPAIR];    // [d][44]

    const int tid = threadIdx.x;
    const int row = blockIdx.x;
    const int bn  = row >> 4;
    const int h   = row & 15;
    const int b   = bn / N_;
    const int pixbase = row * W_;

    // stage geom cells (overlaps softmax loads)
    {
        const int2* g2 = (const int2*)geom;
        const int cbase = bn * D_BINS * HW + h * W_;
        for (int i = tid; i < NPAIR; i += 256) {
            int d = i / W_;
            int w = i - d * W_;
            int2 g = __ldg(&g2[cbase + d * HW + w]);
            s_cell[i] = (b << 14) + g.x * BEVW + g.y;
        }
    }

    // softmax: one warp per w-column
    const int warp = tid >> 5;
    const int lane = tid & 31;
    for (int w = warp; w < W_; w += 8) {
        const float* dp = &g_dep[(pixbase + w) * 64];
        float v0 = (lane < D_BINS)        ? __ldg(&dp[lane])      : -1e30f;
        float v1 = ((lane + 32) < D_BINS) ? __ldg(&dp[lane + 32]) : -1e30f;
        float m = fmaxf(v0, v1);
#pragma unroll
        for (int off = 16; off; off >>= 1)
            m = fmaxf(m, __shfl_xor_sync(0xffffffffu, m, off));
        float e0 = (lane < D_BINS)        ? expf(v0 - m) : 0.f;
        float e1 = ((lane + 32) < D_BINS) ? expf(v1 - m) : 0.f;
        float s = e0 + e1;
#pragma unroll
        for (int off = 16; off; off >>= 1)
            s += __shfl_xor_sync(0xffffffffu, s, off);
        float inv = 1.0f / s;
        if (lane < D_BINS)        s_dep[lane * W_ + w]        = e0 * inv;
        if ((lane + 32) < D_BINS) s_dep[(lane + 32) * W_ + w] = e1 * inv;
    }
    __syncthreads();

    // bin the 2596 points
    for (int p = tid; p < NPAIR; p += 256) {
        int w = p % W_;
        int cell = s_cell[p];
        int slot = atomicAdd(&g_cnt[cell], 1);
        if (slot < CAP)
            g_bin[cell * CAP + slot] =
                make_int2(pixbase + w, __float_as_int(s_dep[p]));
    }
}

// ============================================================================
// K3: GATHER per BEV cell. 2048 blocks x 128 threads; block = 32 cells,
// warp = 8 cells. Records staged in smem unconditionally; point loop in
// chunks of EIGHT -> 8 independent LDG.128 in flight per warp (MLP 8).
// cnt>32 tail (P~9e-5/cell) reads gmem directly.
// ============================================================================
__global__ __launch_bounds__(128, 8) void gather_kernel(float* __restrict__ out)
{
    __shared__ int2  s_rec[GCELLS * STAGE];      // 8 KB
    __shared__ int   s_cnt[GCELLS];
    __shared__ float t[C_CH * (GCELLS + 1)];     // [c][33] 10.6 KB

    const int tid  = threadIdx.x;
    const int warp = tid >> 5;
    const int lane = tid & 31;
    const int b    = blockIdx.x >> 9;            // 512 blocks per batch
    const int yx0  = (blockIdx.x & 511) * GCELLS;
    const int cell0 = (b << 14) + yx0;
    const float4* ctx4 = (const float4*)g_ctx;

    if (tid < GCELLS) {
        int c = g_cnt[cell0 + tid];
        g_cnt[cell0 + tid] = 0;                  // reset for next graph replay
        s_cnt[tid] = (c > CAP) ? CAP : c;
    }
#pragma unroll
    for (int r = 0; r < GCELLS * STAGE / 128; r++) {
        int i  = tid + 128 * r;                  // i = cl*32 + slot
        int cl = i >> 5, slot = i & 31;
        s_rec[i] = g_bin[(cell0 + cl) * CAP + slot];
    }
    __syncthreads();

#pragma unroll
    for (int cc = 0; cc < 8; cc++) {
        const int cl  = warp * 8 + cc;           // local cell 0..31
        const int cnt = s_cnt[cl];
        const int cnt_s = (cnt < STAGE) ? cnt : STAGE;
        const int2* rec = &s_rec[cl * STAGE];

        float4 acc = make_float4(0.f, 0.f, 0.f, 0.f);
        for (int base = 0; base < cnt_s; base += 8) {
            int   pix[8];
            float dep[8];
#pragma unroll
            for (int u = 0; u < 8; u++) {
                int pt  = base + u;
                int idx = (pt < cnt_s) ? pt : (cnt_s - 1);
                int2 rr = rec[idx];              // LDS broadcast
                pix[u] = rr.x;
                dep[u] = (pt < cnt_s) ? __int_as_float(rr.y) : 0.f;
            }
            if (lane < 20) {
#pragma unroll
                for (int u = 0; u < 8; u++) {
                    float4 cv = __ldg(&ctx4[pix[u] * 20 + lane]);
                    acc.x += dep[u] * cv.x;
                    acc.y += dep[u] * cv.y;
                    acc.z += dep[u] * cv.z;
                    acc.w += dep[u] * cv.w;
                }
            }
        }
        // rare overflow tail
        for (int pt = STAGE; pt < cnt; pt++) {
            int2 rr = __ldg(&g_bin[(cell0 + cl) * CAP + pt]);
            float dep0 = __int_as_float(rr.y);
            if (lane < 20) {
                float4 cv = __ldg(&ctx4[rr.x * 20 + lane]);
                acc.x += dep0 * cv.x; acc.y += dep0 * cv.y;
                acc.z += dep0 * cv.z; acc.w += dep0 * cv.w;
            }
        }
        if (lane < 20) {
            int c = lane * 4;
            t[(c + 0) * (GCELLS + 1) + cl] = acc.x;
            t[(c + 1) * (GCELLS + 1) + cl] = acc.y;
            t[(c + 2) * (GCELLS + 1) + cl] = acc.z;
            t[(c + 3) * (GCELLS + 1) + cl] = acc.w;
        }
    }
    __syncthreads();

    float* dst = out + ((size_t)b * C_CH) * (128 * 128) + yx0;
#pragma unroll
    for (int i = tid; i < C_CH * GCELLS; i += 128) {
        int c = i >> 5;
        int j = i & 31;
        dst[(size_t)c * (128 * 128) + j] = t[c * (GCELLS + 1) + j];
    }
}

// ============================================================================
extern "C" void kernel_launch(void* const* d_in, const int* in_sizes, int n_in,
                              void* d_out, int out_size)
{
    const float* img  = (const float*)d_in[0];
    const float* wd   = (const float*)d_in[4];
    const float* bd   = (const float*)d_in[5];
    const int*   geom = (const int*)d_in[6];
    float* out = (float*)d_out;

    gemm_kernel<<<B_ * N_ * H_ * 3, 128>>>(img, wd, bd);
    softmax_bin_kernel<<<B_ * N_ * H_, 256>>>(geom);
    gather_kernel<<<2048, 128>>>(out);
}

// round 10
// speedup vs baseline: 1.4385x; 1.0513x over previous
#include <cuda_runtime.h>
#include <cstdint>

#define D_BINS 59
#define C_CH   80
#define O_TOT  139
#define B_     4
#define N_     6
#define CIN    256
#define H_     16
#define W_     44
#define HW     704              // H_*W_
#define NPIX   (B_*N_*H_*W_)    // 16896 = 264 * 64
#define NCELL  (B_*128*128)     // 65536
#define BEVW   128
#define NPAIR  (D_BINS*W_)      // 2596 (d,w) pairs per row
#define CAP    64               // bin capacity: Poisson(15.2), P(>=64)~1e-28/cell — safe
#define STAGE  32               // records staged in smem per cell in gather
#define GCELLS 32               // cells per gather block
#define OT3    48               // outputs per o-third

// ---- device scratch (no allocations; zero-initialized at load) ----
__device__ float g_dep[NPIX*64];           // [pix][o<59] depth logits, 4.3 MB
__device__ float g_ctx[NPIX*C_CH];         // [pix][c] fp32 ctx, 5.4 MB (L2-resident)
__device__ int   g_cnt[NCELL];             // per-cell counts (reset by gather)
__device__ int2  g_bin[NCELL*CAP];         // {pix, depth-bits}, 33.5 MB

// ============================================================================
// K1: GEMM. Block = (64-px strip, o-third): 48o x 64px x 256c, 128 threads.
// Thread tile 6o x 4px. ws stored as [c][o_tile][8] (32B-aligned groups) ->
// weights = LDS.128 + LDS.64; x = LDS.128. 3 LDS per 24 FFMA (~85% FFMA mix).
// Grid 792 blocks -> 5.35/SM, perfect 4-warp SMSP balance, ~8 blocks/SM.
// ============================================================================
__global__ __launch_bounds__(128) void gemm_kernel(
    const float* __restrict__ img, const float* __restrict__ wd,
    const float* __restrict__ bd)
{
    __shared__ float ws[32 * 64];    // [c][o_tile][8], 8 KB
    __shared__ float xs[32 * 64];    // [c][px]        8 KB
    __shared__ int   s_base[64];     // per-px img base offset

    const int tid   = threadIdx.x;
    const int blk   = blockIdx.x;
    const int pxb   = blk / 3;
    const int third = blk - pxb * 3;
    const int px0   = pxb * 64;
    const int o0    = third * OT3;
    const float4* w4 = (const float4*)wd;   // [139][64] float4

    if (tid < 64) {
        int p  = px0 + tid;
        int bn = p / HW;
        int hw = p - bn * HW;
        s_base[tid] = bn * (CIN * HW) + hw;
    }

    const int pt = tid & 15;   // px-tile (4 px), 16 tiles
    const int ot = tid >> 4;   // o-tile (6 o),   8 tiles

    float acc[6][4];
#pragma unroll
    for (int j = 0; j < 6; j++)
#pragma unroll
        for (int k = 0; k < 4; k++) acc[j][k] = 0.f;

    for (int ck = 0; ck < 8; ck++) {        // 8 chunks of 32 input channels
        __syncthreads();                    // prev compute done (also covers s_base)
        // stage weights: idx = o_l*8 + c4, o_l < 48
#pragma unroll
        for (int r = 0; r < 3; r++) {
            int idx = tid + 128 * r;
            int o_l = idx >> 3;
            int c4  = idx & 7;
            float4 v = make_float4(0.f, 0.f, 0.f, 0.f);
            if (o0 + o_l < O_TOT) v = w4[(o0 + o_l) * 64 + ck * 8 + c4];
            int otl = o_l / 6;
            int oin = o_l - otl * 6;
            ws[((c4 * 4 + 0) * 8 + otl) * 8 + oin] = v.x;
            ws[((c4 * 4 + 1) * 8 + otl) * 8 + oin] = v.y;
            ws[((c4 * 4 + 2) * 8 + otl) * 8 + oin] = v.z;
            ws[((c4 * 4 + 3) * 8 + otl) * 8 + oin] = v.w;
        }
        // stage x: 32c x 64px, coalesced per c-row
#pragma unroll
        for (int r = 0; r < 16; r++) {
            int i  = tid + 128 * r;
            int c  = i >> 6;
            int px = i & 63;
            xs[i] = img[s_base[px] + (ck * 32 + c) * HW];
        }
        __syncthreads();

#pragma unroll 4
        for (int c = 0; c < 32; c++) {
            const float* wp = &ws[(c * 8 + ot) * 8];
            float4 wa = *(const float4*)wp;           // LDS.128 (32B-aligned)
            float2 wb = *(const float2*)(wp + 4);     // LDS.64
            float4 xv = *(const float4*)&xs[c * 64 + pt * 4];  // LDS.128
            float wv[6] = {wa.x, wa.y, wa.z, wa.w, wb.x, wb.y};
#pragma unroll
            for (int j = 0; j < 6; j++) {
                acc[j][0] += wv[j] * xv.x;
                acc[j][1] += wv[j] * xv.y;
                acc[j][2] += wv[j] * xv.z;
                acc[j][3] += wv[j] * xv.w;
            }
        }
    }

    // store: depth logits -> g_dep[pix][o], ctx -> g_ctx[pix][o-59]
#pragma unroll
    for (int j = 0; j < 6; j++) {
        int o_g = o0 + ot * 6 + j;
        if (o_g < O_TOT) {
            float bias = __ldg(&bd[o_g]);
#pragma unroll
            for (int k = 0; k < 4; k++) {
                int p = px0 + pt * 4 + k;
                float v = acc[j][k] + bias;
                if (o_g < D_BINS) g_dep[p * 64 + o_g]              = v;
                else              g_ctx[p * C_CH + (o_g - D_BINS)] = v;
            }
        }
    }
}

// ============================================================================
// K2: softmax(59) over g_dep + cell binning. 384 blocks (one per row) x 256.
// ============================================================================
__global__ __launch_bounds__(256) void softmax_bin_kernel(const int* __restrict__ geom)
{
    __shared__ float s_dep[NPAIR];     // [d][44]
    __shared__ int   s_cell[NPAIR];    // [d][44]

    const int tid = threadIdx.x;
    const int row = blockIdx.x;
    const int bn  = row >> 4;
    const int h   = row & 15;
    const int b   = bn / N_;
    const int pixbase = row * W_;

    // stage geom cells (overlaps softmax loads)
    {
        const int2* g2 = (const int2*)geom;
        const int cbase = bn * D_BINS * HW + h * W_;
        for (int i = tid; i < NPAIR; i += 256) {
            int d = i / W_;
            int w = i - d * W_;
            int2 g = __ldg(&g2[cbase + d * HW + w]);
            s_cell[i] = (b << 14) + g.x * BEVW + g.y;
        }
    }

    // softmax: one warp per w-column
    const int warp = tid >> 5;
    const int lane = tid & 31;
    for (int w = warp; w < W_; w += 8) {
        const float* dp = &g_dep[(pixbase + w) * 64];
        float v0 = (lane < D_BINS)        ? __ldg(&dp[lane])      : -1e30f;
        float v1 = ((lane + 32) < D_BINS) ? __ldg(&dp[lane + 32]) : -1e30f;
        float m = fmaxf(v0, v1);
#pragma unroll
        for (int off = 16; off; off >>= 1)
            m = fmaxf(m, __shfl_xor_sync(0xffffffffu, m, off));
        float e0 = (lane < D_BINS)        ? expf(v0 - m) : 0.f;
        float e1 = ((lane + 32) < D_BINS) ? expf(v1 - m) : 0.f;
        float s = e0 + e1;
#pragma unroll
        for (int off = 16; off; off >>= 1)
            s += __shfl_xor_sync(0xffffffffu, s, off);
        float inv = 1.0f / s;
        if (lane < D_BINS)        s_dep[lane * W_ + w]        = e0 * inv;
        if ((lane + 32) < D_BINS) s_dep[(lane + 32) * W_ + w] = e1 * inv;
    }
    __syncthreads();

    // bin the 2596 points
    for (int p = tid; p < NPAIR; p += 256) {
        int w = p % W_;
        int cell = s_cell[p];
        int slot = atomicAdd(&g_cnt[cell], 1);
        if (slot < CAP)
            g_bin[cell * CAP + slot] =
                make_int2(pixbase + w, __float_as_int(s_dep[p]));
    }
}

// ============================================================================
// K3: GATHER per BEV cell. 2048 blocks x 128 threads; block = 32 cells,
// warp = 8 cells. Records staged in smem unconditionally; point loop in
// chunks of 8 -> 8 independent LDG.128 in flight per warp (MLP 8).
// cnt>32 tail (P~9e-5/cell) reads gmem directly.
// ============================================================================
__global__ __launch_bounds__(128, 8) void gather_kernel(float* __restrict__ out)
{
    __shared__ int2  s_rec[GCELLS * STAGE];      // 8 KB
    __shared__ int   s_cnt[GCELLS];
    __shared__ float t[C_CH * (GCELLS + 1)];     // [c][33] 10.6 KB

    const int tid  = threadIdx.x;
    const int warp = tid >> 5;
    const int lane = tid & 31;
    const int b    = blockIdx.x >> 9;            // 512 blocks per batch
    const int yx0  = (blockIdx.x & 511) * GCELLS;
    const int cell0 = (b << 14) + yx0;
    const float4* ctx4 = (const float4*)g_ctx;

    if (tid < GCELLS) {
        int c = g_cnt[cell0 + tid];
        g_cnt[cell0 + tid] = 0;                  // reset for next graph replay
        s_cnt[tid] = (c > CAP) ? CAP : c;
    }
#pragma unroll
    for (int r = 0; r < GCELLS * STAGE / 128; r++) {
        int i  = tid + 128 * r;                  // i = cl*32 + slot
        int cl = i >> 5, slot = i & 31;
        s_rec[i] = g_bin[(cell0 + cl) * CAP + slot];
    }
    __syncthreads();

#pragma unroll
    for (int cc = 0; cc < 8; cc++) {
        const int cl  = warp * 8 + cc;           // local cell 0..31
        const int cnt = s_cnt[cl];
        const int cnt_s = (cnt < STAGE) ? cnt : STAGE;
        const int2* rec = &s_rec[cl * STAGE];

        float4 acc = make_float4(0.f, 0.f, 0.f, 0.f);
        for (int base = 0; base < cnt_s; base += 8) {
            int   pix[8];
            float dep[8];
#pragma unroll
            for (int u = 0; u < 8; u++) {
                int pt  = base + u;
                int idx = (pt < cnt_s) ? pt : (cnt_s - 1);
                int2 rr = rec[idx];              // LDS broadcast
                pix[u] = rr.x;
                dep[u] = (pt < cnt_s) ? __int_as_float(rr.y) : 0.f;
            }
            if (lane < 20) {
#pragma unroll
                for (int u = 0; u < 8; u++) {
                    float4 cv = __ldg(&ctx4[pix[u] * 20 + lane]);
                    acc.x += dep[u] * cv.x;
                    acc.y += dep[u] * cv.y;
                    acc.z += dep[u] * cv.z;
                    acc.w += dep[u] * cv.w;
                }
            }
        }
        // rare overflow tail
        for (int pt = STAGE; pt < cnt; pt++) {
            int2 rr = __ldg(&g_bin[(cell0 + cl) * CAP + pt]);
            float dep0 = __int_as_float(rr.y);
            if (lane < 20) {
                float4 cv = __ldg(&ctx4[rr.x * 20 + lane]);
                acc.x += dep0 * cv.x; acc.y += dep0 * cv.y;
                acc.z += dep0 * cv.z; acc.w += dep0 * cv.w;
            }
        }
        if (lane < 20) {
            int c = lane * 4;
            t[(c + 0) * (GCELLS + 1) + cl] = acc.x;
            t[(c + 1) * (GCELLS + 1) + cl] = acc.y;
            t[(c + 2) * (GCELLS + 1) + cl] = acc.z;
            t[(c + 3) * (GCELLS + 1) + cl] = acc.w;
        }
    }
    __syncthreads();

    float* dst = out + ((size_t)b * C_CH) * (128 * 128) + yx0;
#pragma unroll
    for (int i = tid; i < C_CH * GCELLS; i += 128) {
        int c = i >> 5;
        int j = i & 31;
        dst[(size_t)c * (128 * 128) + j] = t[c * (GCELLS + 1) + j];
    }
}

// ============================================================================
extern "C" void kernel_launch(void* const* d_in, const int* in_sizes, int n_in,
                              void* d_out, int out_size)
{
    const float* img  = (const float*)d_in[0];
    const float* wd   = (const float*)d_in[4];
    const float* bd   = (const float*)d_in[5];
    const int*   geom = (const int*)d_in[6];
    float* out = (float*)d_out;

    gemm_kernel<<<(NPIX / 64) * 3, 128>>>(img, wd, bd);
    softmax_bin_kernel<<<B_ * N_ * H_, 256>>>(geom);
    gather_kernel<<<2048, 128>>>(out);
}